// round 15
// baseline (speedup 1.0000x reference)
#include <cuda_runtime.h>
#include <cuda_bf16.h>
#include <cstdint>
#include <cstddef>

// Pairwise Euclidean distance, B=8192, K=256, D=3072, fp32.
// out[b,k] = sqrt(max(||x||^2 + ||c||^2 - 2 x.c, eps))
// R15: BOTH operands prepassed to bf16 (+fp32 norms). Main kernel is a pure
// cp.async bf16 mma.sync GEMM: dual 256-thread k-parity pipelines (R8-proven),
// no LDG staging / cvt / STS / atomics in the mainloop.

#define BB 8192
#define KK 256
#define DD 3072
#define BM 128
#define BN 128
#define BK 32
#define NT (DD / BK)            // 96 k-tiles
#define NTG (NT / 2)            // 48 per group
#define NTHREADS 512
#define EPS_F 1e-12f

#define ROW_B 80                // 32 bf16 + pad: ldmatrix conflict-free
#define TILE_B (128 * ROW_B)    // 10240
#define STAGE_B (2 * TILE_B)    // 20480 (A then B)
#define GSTEP (2 * STAGE_B)     // group-local stage stride
#define NSTAGE 8
#define OFF_CSQ  (NSTAGE * STAGE_B)          // 163840
#define SMEM_BYTES (OFF_CSQ + 512)
#define STASH_STRIDE 132

__device__ __nv_bfloat16 g_xb[BB * DD];   // inputs bf16 (50 MB, L2-resident)
__device__ __nv_bfloat16 g_cb[KK * DD];   // centers bf16
__device__ float g_xsq[BB];
__device__ float g_csq[KK];

static __device__ __forceinline__ uint32_t s2u(const void* p) {
    uint32_t a;
    asm("{.reg .u64 t; cvta.to.shared.u64 t, %1; cvt.u32.u64 %0, t;}"
        : "=r"(a) : "l"(p));
    return a;
}

#define LDSM_X4(r0, r1, r2, r3, a)                                            \
    asm volatile("ldmatrix.sync.aligned.m8n8.x4.shared.b16 {%0,%1,%2,%3}, [%4];" \
                 : "=r"(r0), "=r"(r1), "=r"(r2), "=r"(r3) : "r"(a))

#define GBAR(id) asm volatile("bar.sync %0, 256;" :: "r"(id) : "memory")

// ---------------- prepass: fp32 -> bf16 + row norm (row per block) ----------------
template <int NROW>
__global__ void __launch_bounds__(128, 8)
prep_kernel(const float* __restrict__ src_f, __nv_bfloat16* __restrict__ dst_b,
            float* __restrict__ nrm)
{
    const int row = blockIdx.x;
    const float4* src = reinterpret_cast<const float4*>(src_f + (size_t)row * DD);
    uint2* dst = reinterpret_cast<uint2*>(dst_b + (size_t)row * DD);
    float s = 0.f;
    #pragma unroll
    for (int i = 0; i < 6; i++) {
        const int q = threadIdx.x + i * 128;
        float4 v = src[q];
        s += v.x * v.x + v.y * v.y + v.z * v.z + v.w * v.w;
        __nv_bfloat162 p0 = __float22bfloat162_rn(make_float2(v.x, v.y));
        __nv_bfloat162 p1 = __float22bfloat162_rn(make_float2(v.z, v.w));
        uint2 u;
        u.x = *reinterpret_cast<uint32_t*>(&p0);
        u.y = *reinterpret_cast<uint32_t*>(&p1);
        dst[q] = u;
    }
    #pragma unroll
    for (int o = 16; o > 0; o >>= 1)
        s += __shfl_xor_sync(0xFFFFFFFFu, s, o);
    __shared__ float red[4];
    if ((threadIdx.x & 31) == 0) red[threadIdx.x >> 5] = s;
    __syncthreads();
    if (threadIdx.x == 0)
        nrm[row] = red[0] + red[1] + red[2] + red[3];
}

// ---------------- main GEMM: pure cp.async dual pipeline ----------------
__global__ void __launch_bounds__(NTHREADS, 1)
rbf_cp_kernel(float* __restrict__ out)
{
    extern __shared__ __align__(16) char smem[];
    const uint32_t sb = s2u(smem);
    const int tid  = threadIdx.x;
    const int wid  = tid >> 5;
    const int lane = tid & 31;
    const int bm = blockIdx.y;
    const int bn = blockIdx.x;

    const int g   = wid >> 3;          // k-parity group 0/1
    const int gt  = tid & 255;
    const int bar = g + 1;

    float* csq_s = (float*)(smem + OFF_CSQ);
    if (tid < 128) csq_s[tid] = g_csq[bn * BN + tid];
    __syncthreads();

    const uint32_t sbg = sb + (uint32_t)g * STAGE_B;

    // ---- A producer: cp.async bf16, row = gt>>1, chunks {c, c+2}, c = gt&1 ----
    const int arow = gt >> 1;          // 0..127
    const int ac   = gt & 1;
    const __nv_bfloat16* pA = g_xb + (size_t)(bm * BM + arow) * DD + g * BK + ac * 8;
    const uint32_t adst = (uint32_t)arow * ROW_B + (uint32_t)ac * 16;
    // ---- B producer: rows br, br+64 ----
    const int br = gt >> 2;            // 0..63
    const int bc = gt & 3;
    const __nv_bfloat16* pB0 = g_cb + (size_t)(bn * BN + br) * DD + g * BK + bc * 8;
    const __nv_bfloat16* pB1 = pB0 + (size_t)64 * DD;
    const uint32_t bdst = (uint32_t)br * ROW_B + (uint32_t)bc * 16 + (uint32_t)TILE_B;

    auto produce = [&](int i) {
        const uint32_t base = sbg + (uint32_t)(i & 3) * GSTEP;
        asm volatile("cp.async.cg.shared.global [%0], [%1], 16;"
                     :: "r"(base + adst), "l"(pA) : "memory");
        asm volatile("cp.async.cg.shared.global [%0], [%1], 16;"
                     :: "r"(base + adst + 32), "l"(pA + 16) : "memory");
        asm volatile("cp.async.cg.shared.global [%0], [%1], 16;"
                     :: "r"(base + bdst), "l"(pB0) : "memory");
        asm volatile("cp.async.cg.shared.global [%0], [%1], 16;"
                     :: "r"(base + bdst + (uint32_t)(64 * ROW_B)), "l"(pB1) : "memory");
        asm volatile("cp.async.commit_group;" ::: "memory");
        pA += 64; pB0 += 64; pB1 += 64;   // 2 global k-tiles
    };

    // ---- compute mapping: per group 4(M)x2(N), warp tile 32x64 (R8-proven) ----
    const int w8 = wid & 7;
    const int wm = w8 & 3;
    const int wn = w8 >> 2;
    const int fr = lane >> 2;
    const int fc = (lane & 3) * 2;
    const int lg = lane >> 3;
    const int ri = lane & 7;
    const uint32_t lm_off = (uint32_t)(((lg & 1) * 8 + ri) * ROW_B + (lg >> 1) * 16);
    const uint32_t a_off = (uint32_t)(wm * 32 * ROW_B) + lm_off;
    const uint32_t b_off = (uint32_t)(wn * 64 * ROW_B) + lm_off + (uint32_t)TILE_B;

    float acc[2][8][4];
    #pragma unroll
    for (int i = 0; i < 2; i++)
        #pragma unroll
        for (int j = 0; j < 8; j++)
            #pragma unroll
            for (int q = 0; q < 4; q++) acc[i][j][q] = 0.f;

    // ---- prologue ----
    produce(0);
    produce(1);
    asm volatile("cp.async.wait_group 1;" ::: "memory");
    GBAR(bar);

    // ---- mainloop ----
    #pragma unroll 1
    for (int i = 0; i < NTG; i++) {
        const uint32_t st = sbg + (uint32_t)(i & 3) * GSTEP;
        const uint32_t stA = st + a_off;
        const uint32_t stB = st + b_off;

        #pragma unroll
        for (int ks = 0; ks < 2; ks++) {
            const uint32_t kof = (uint32_t)ks * 32;
            uint32_t a[2][4], b[4][4];
            LDSM_X4(a[0][0], a[0][1], a[0][2], a[0][3], stA + kof);
            LDSM_X4(a[1][0], a[1][1], a[1][2], a[1][3], stA + kof + 16 * ROW_B);
            LDSM_X4(b[0][0], b[0][1], b[0][2], b[0][3], stB + kof);
            LDSM_X4(b[1][0], b[1][1], b[1][2], b[1][3], stB + kof + 16 * ROW_B);
            LDSM_X4(b[2][0], b[2][1], b[2][2], b[2][3], stB + kof + 32 * ROW_B);
            LDSM_X4(b[3][0], b[3][1], b[3][2], b[3][3], stB + kof + 48 * ROW_B);
            #pragma unroll
            for (int im = 0; im < 2; im++)
                #pragma unroll
                for (int j = 0; j < 8; j++) {
                    const int jb = j >> 1, pp = j & 1;
                    asm volatile(
                        "mma.sync.aligned.m16n8k16.row.col.f32.bf16.bf16.f32 "
                        "{%0,%1,%2,%3}, {%4,%5,%6,%7}, {%8,%9}, {%0,%1,%2,%3};\n"
                        : "+f"(acc[im][j][0]), "+f"(acc[im][j][1]),
                          "+f"(acc[im][j][2]), "+f"(acc[im][j][3])
                        : "r"(a[im][0]), "r"(a[im][1]), "r"(a[im][2]), "r"(a[im][3]),
                          "r"(b[jb][pp]), "r"(b[jb][pp + 2]));
                }
        }

        if (i + 2 < NTG) {
            produce(i + 2);
            asm volatile("cp.async.wait_group 1;" ::: "memory");
        } else {
            asm volatile("cp.async.wait_group 0;" ::: "memory");
        }
        GBAR(bar);
    }

    __syncthreads();

    // ---- split-k merge + fused epilogue (xsq from global) ----
    float* stash = (float*)smem;
    if (g == 1) {
        #pragma unroll
        for (int im = 0; im < 2; im++)
            #pragma unroll
            for (int hf = 0; hf < 2; hf++) {
                const int row = wm * 32 + im * 16 + hf * 8 + fr;
                #pragma unroll
                for (int j = 0; j < 8; j++) {
                    const int col = wn * 64 + j * 8 + fc;
                    *reinterpret_cast<float2*>(&stash[row * STASH_STRIDE + col]) =
                        make_float2(acc[im][j][hf * 2], acc[im][j][hf * 2 + 1]);
                }
            }
    }
    __syncthreads();
    if (g == 0) {
        #pragma unroll
        for (int im = 0; im < 2; im++)
            #pragma unroll
            for (int hf = 0; hf < 2; hf++) {
                const int row = wm * 32 + im * 16 + hf * 8 + fr;
                const float xq = g_xsq[bm * BM + row];
                float* orow = out + ((size_t)bm * BM + row) * KK + bn * BN;
                #pragma unroll
                for (int j = 0; j < 8; j++) {
                    const int col = wn * 64 + j * 8 + fc;
                    const float2 o = *reinterpret_cast<const float2*>(
                        &stash[row * STASH_STRIDE + col]);
                    const float cr0 = acc[im][j][hf * 2] + o.x;
                    const float cr1 = acc[im][j][hf * 2 + 1] + o.y;
                    const float d0 = sqrtf(fmaxf(xq + csq_s[col] - 2.f * cr0, EPS_F));
                    const float d1 = sqrtf(fmaxf(xq + csq_s[col + 1] - 2.f * cr1, EPS_F));
                    *reinterpret_cast<float2*>(orow + col) = make_float2(d0, d1);
                }
            }
    }
}

extern "C" void kernel_launch(void* const* d_in, const int* in_sizes, int n_in,
                              void* d_out, int out_size)
{
    const float* X = (const float*)d_in[0];   // inputs  [8192, 3072] fp32
    const float* C = (const float*)d_in[1];   // centers [256, 3072]  fp32
    float* out = (float*)d_out;               // [8192, 256] fp32

    __nv_bfloat16 *xb_p, *cb_p;
    float *xsq_p, *csq_p;
    cudaGetSymbolAddress((void**)&xb_p, g_xb);
    cudaGetSymbolAddress((void**)&cb_p, g_cb);
    cudaGetSymbolAddress((void**)&xsq_p, g_xsq);
    cudaGetSymbolAddress((void**)&csq_p, g_csq);

    prep_kernel<KK><<<KK, 128>>>(C, cb_p, csq_p);
    prep_kernel<BB><<<BB, 128>>>(X, xb_p, xsq_p);

    cudaFuncSetAttribute(rbf_cp_kernel,
                         cudaFuncAttributeMaxDynamicSharedMemorySize, SMEM_BYTES);
    dim3 grid(KK / BN, BB / BM);              // (2, 64) = 128 CTAs
    rbf_cp_kernel<<<grid, NTHREADS, SMEM_BYTES>>>(out);
}

// round 16
// speedup vs baseline: 1.4204x; 1.4204x over previous
#include <cuda_runtime.h>
#include <cuda_bf16.h>
#include <cstdint>
#include <cstddef>

// Pairwise Euclidean distance, B=8192, K=256, D=3072, fp32.
// out[b,k] = sqrt(max(||x||^2 + ||c||^2 - 2 x.c, eps))
// R16 = R8 (proven 64.0us) with ONE structural change: TWO k-tiles per
// barrier (pair double-buffering in the 4-stage subring) so tile t+1's LDSM
// burst overlaps tile t's MMA drain. Dual independent 256-thread k-parity
// pipelines, named barriers, cp.async B (bf16 prepass), fused norms.

#define BB 8192
#define KK 256
#define DD 3072
#define BM 128
#define BN 128
#define BK 32
#define NT (DD / BK)            // 96 k-tiles
#define NTG (NT / 2)            // 48 per group
#define NITER (NTG / 2)         // 24 barrier segments per group
#define NTHREADS 512
#define EPS_F 1e-12f

#define ROW_B 80                // 32 bf16 + pad: ldmatrix conflict-free
#define TILE_B (128 * ROW_B)    // 10240
#define STAGE_B (2 * TILE_B)    // 20480 (A then B)
#define GSTEP (2 * STAGE_B)     // group-local stage stride
#define NSTAGE 8
#define OFF_XSQ  (NSTAGE * STAGE_B)          // 163840
#define OFF_CSQ  (OFF_XSQ + 512)
#define SMEM_BYTES (OFF_CSQ + 512)
#define STASH_STRIDE 132

__device__ __nv_bfloat16 g_cb[KK * DD];   // centers bf16
__device__ float g_csq[KK];               // ||c||^2

static __device__ __forceinline__ uint32_t s2u(const void* p) {
    uint32_t a;
    asm("{.reg .u64 t; cvta.to.shared.u64 t, %1; cvt.u32.u64 %0, t;}"
        : "=r"(a) : "l"(p));
    return a;
}

#define LDSM_X4(r0, r1, r2, r3, a)                                            \
    asm volatile("ldmatrix.sync.aligned.m8n8.x4.shared.b16 {%0,%1,%2,%3}, [%4];" \
                 : "=r"(r0), "=r"(r1), "=r"(r2), "=r"(r3) : "r"(a))

#define GBAR(id) asm volatile("bar.sync %0, 256;" :: "r"(id) : "memory")

// ---------------- prepass: centers fp32 -> bf16, csq ----------------
__global__ void __launch_bounds__(128, 8)
prep_c_kernel(const float* __restrict__ C)
{
    const int row = blockIdx.x;
    const float4* src = reinterpret_cast<const float4*>(C + (size_t)row * DD);
    uint2* dst = reinterpret_cast<uint2*>(g_cb + (size_t)row * DD);
    float s = 0.f;
    #pragma unroll
    for (int i = 0; i < 6; i++) {
        const int q = threadIdx.x + i * 128;
        float4 v = src[q];
        s += v.x * v.x + v.y * v.y + v.z * v.z + v.w * v.w;
        __nv_bfloat162 p0 = __float22bfloat162_rn(make_float2(v.x, v.y));
        __nv_bfloat162 p1 = __float22bfloat162_rn(make_float2(v.z, v.w));
        uint2 u;
        u.x = *reinterpret_cast<uint32_t*>(&p0);
        u.y = *reinterpret_cast<uint32_t*>(&p1);
        dst[q] = u;
    }
    #pragma unroll
    for (int o = 16; o > 0; o >>= 1)
        s += __shfl_xor_sync(0xFFFFFFFFu, s, o);
    __shared__ float red[4];
    if ((threadIdx.x & 31) == 0) red[threadIdx.x >> 5] = s;
    __syncthreads();
    if (threadIdx.x == 0)
        g_csq[row] = red[0] + red[1] + red[2] + red[3];
}

// ---------------- main GEMM ----------------
__global__ void __launch_bounds__(NTHREADS, 1)
rbf_pair_kernel(const float* __restrict__ X, float* __restrict__ out)
{
    extern __shared__ __align__(16) char smem[];
    const uint32_t sb = s2u(smem);
    const int tid  = threadIdx.x;
    const int wid  = tid >> 5;
    const int lane = tid & 31;
    const int bm = blockIdx.y;
    const int bn = blockIdx.x;

    const int g   = wid >> 3;          // k-parity group 0/1
    const int gt  = tid & 255;
    const int bar = g + 1;

    float* xsq_s = (float*)(smem + OFF_XSQ);
    float* csq_s = (float*)(smem + OFF_CSQ);
    if (tid < 128) {
        xsq_s[tid] = 0.f;
        csq_s[tid] = g_csq[bn * BN + tid];
    }
    __syncthreads();

    const uint32_t sbg = sb + (uint32_t)g * STAGE_B;

    // ---- A producer (R8 mapping): rows ar+32j, quarter-warp = 1 cache line ----
    const int ar = gt >> 3;            // 0..31
    const int c4 = gt & 7;
    const float* gA = X + (size_t)(bm * BM) * DD;
    const int row4 = DD / 4;
    float4 ra[4];
    float xs[4] = {0.f, 0.f, 0.f, 0.f};

    auto ldgA = [&](int i) {           // group-local tile i -> kt = 2i+g
        const int k4 = (2 * i + g) * (BK / 4);
        #pragma unroll
        for (int p = 0; p < 4; p++)
            ra[p] = reinterpret_cast<const float4*>(gA)
                        [(size_t)(p * 32 + ar) * row4 + k4 + c4];
    };
    auto stsA = [&](int i) {
        const uint32_t base = sbg + (uint32_t)(i & 3) * GSTEP
                            + (uint32_t)ar * ROW_B + (uint32_t)c4 * 8;
        #pragma unroll
        for (int p = 0; p < 4; p++) {
            float4 v = ra[p];
            xs[p] += v.x * v.x + v.y * v.y + v.z * v.z + v.w * v.w;
            __nv_bfloat162 q0 = __float22bfloat162_rn(make_float2(v.x, v.y));
            __nv_bfloat162 q1 = __float22bfloat162_rn(make_float2(v.z, v.w));
            asm volatile("st.shared.v2.b32 [%0], {%1,%2};"
                         :: "r"(base + (uint32_t)(p * 32 * ROW_B)),
                            "r"(*reinterpret_cast<uint32_t*>(&q0)),
                            "r"(*reinterpret_cast<uint32_t*>(&q1)) : "memory");
        }
    };

    // ---- B producer (R8 mapping): cp.async ----
    const int br = gt >> 2;            // rows br, br+64
    const int bc = gt & 3;
    const __nv_bfloat16* gB = g_cb + (size_t)(bn * BN + br) * DD + g * BK + bc * 8;
    const __nv_bfloat16* gB1 = gB + (size_t)64 * DD;
    const uint32_t bdst = (uint32_t)br * ROW_B + (uint32_t)bc * 16 + (uint32_t)TILE_B;
    auto cpB = [&](int i) {
        const uint32_t base = sbg + (uint32_t)(i & 3) * GSTEP + bdst;
        asm volatile("cp.async.cg.shared.global [%0], [%1], 16;"
                     :: "r"(base), "l"(gB + i * 64) : "memory");
        asm volatile("cp.async.cg.shared.global [%0], [%1], 16;"
                     :: "r"(base + (uint32_t)(64 * ROW_B)), "l"(gB1 + i * 64) : "memory");
        asm volatile("cp.async.commit_group;" ::: "memory");
    };

    // ---- compute mapping: per group 4(M)x2(N), warp tile 32x64 ----
    const int w8 = wid & 7;
    const int wm = w8 & 3;
    const int wn = w8 >> 2;
    const int fr = lane >> 2;
    const int fc = (lane & 3) * 2;
    const int lg = lane >> 3;
    const int ri = lane & 7;
    const uint32_t lm_off = (uint32_t)(((lg & 1) * 8 + ri) * ROW_B + (lg >> 1) * 16);
    const uint32_t a_off = (uint32_t)(wm * 32 * ROW_B) + lm_off;
    const uint32_t b_off = (uint32_t)(wn * 64 * ROW_B) + lm_off + (uint32_t)TILE_B;

    float acc[2][8][4];
    #pragma unroll
    for (int i = 0; i < 2; i++)
        #pragma unroll
        for (int j = 0; j < 8; j++)
            #pragma unroll
            for (int q = 0; q < 4; q++) acc[i][j][q] = 0.f;

    // per-tile MMA body (identical to R8's)
    auto mma_tile = [&](int t) {
        const uint32_t st = sbg + (uint32_t)(t & 3) * GSTEP;
        const uint32_t stA = st + a_off;
        const uint32_t stB = st + b_off;
        #pragma unroll
        for (int ks = 0; ks < 2; ks++) {
            const uint32_t kof = (uint32_t)ks * 32;
            uint32_t a[2][4], b[4][4];
            LDSM_X4(a[0][0], a[0][1], a[0][2], a[0][3], stA + kof);
            LDSM_X4(a[1][0], a[1][1], a[1][2], a[1][3], stA + kof + 16 * ROW_B);
            LDSM_X4(b[0][0], b[0][1], b[0][2], b[0][3], stB + kof);
            LDSM_X4(b[1][0], b[1][1], b[1][2], b[1][3], stB + kof + 16 * ROW_B);
            LDSM_X4(b[2][0], b[2][1], b[2][2], b[2][3], stB + kof + 32 * ROW_B);
            LDSM_X4(b[3][0], b[3][1], b[3][2], b[3][3], stB + kof + 48 * ROW_B);
            #pragma unroll
            for (int im = 0; im < 2; im++)
                #pragma unroll
                for (int j = 0; j < 8; j++) {
                    const int jb = j >> 1, pp = j & 1;
                    asm volatile(
                        "mma.sync.aligned.m16n8k16.row.col.f32.bf16.bf16.f32 "
                        "{%0,%1,%2,%3}, {%4,%5,%6,%7}, {%8,%9}, {%0,%1,%2,%3};\n"
                        : "+f"(acc[im][j][0]), "+f"(acc[im][j][1]),
                          "+f"(acc[im][j][2]), "+f"(acc[im][j][3])
                        : "r"(a[im][0]), "r"(a[im][1]), "r"(a[im][2]), "r"(a[im][3]),
                          "r"(b[jb][pp]), "r"(b[jb][pp + 2]));
                }
        }
    };

    // ---- prologue: fill pair {0,1} ----
    ldgA(0); stsA(0);
    ldgA(1); stsA(1);
    cpB(0); cpB(1);
    asm volatile("cp.async.wait_group 0;" ::: "memory");
    GBAR(bar);

    // ---- mainloop: 24 two-tile segments ----
    #pragma unroll 1
    for (int j = 0; j < NITER; j++) {
        const int t0 = 2 * j, t1 = 2 * j + 1;

        if (t0 + 2 < NTG) { cpB(t0 + 2); ldgA(t0 + 2); }
        mma_tile(t0);
        if (t0 + 2 < NTG) stsA(t0 + 2);

        if (t1 + 2 < NTG) { cpB(t1 + 2); ldgA(t1 + 2); }
        mma_tile(t1);
        if (t1 + 2 < NTG) stsA(t1 + 2);

        asm volatile("cp.async.wait_group 0;" ::: "memory");
        GBAR(bar);
    }

    // ---- norms ----
    #pragma unroll
    for (int p = 0; p < 4; p++)
        atomicAdd(&xsq_s[p * 32 + ar], xs[p]);
    __syncthreads();

    // ---- split-k merge + fused epilogue (R8 verbatim) ----
    float* stash = (float*)smem;
    if (g == 1) {
        #pragma unroll
        for (int im = 0; im < 2; im++)
            #pragma unroll
            for (int hf = 0; hf < 2; hf++) {
                const int row = wm * 32 + im * 16 + hf * 8 + fr;
                #pragma unroll
                for (int j = 0; j < 8; j++) {
                    const int col = wn * 64 + j * 8 + fc;
                    *reinterpret_cast<float2*>(&stash[row * STASH_STRIDE + col]) =
                        make_float2(acc[im][j][hf * 2], acc[im][j][hf * 2 + 1]);
                }
            }
    }
    __syncthreads();
    if (g == 0) {
        #pragma unroll
        for (int im = 0; im < 2; im++)
            #pragma unroll
            for (int hf = 0; hf < 2; hf++) {
                const int row = wm * 32 + im * 16 + hf * 8 + fr;
                const float xq = xsq_s[row];
                float* orow = out + ((size_t)bm * BM + row) * KK + bn * BN;
                #pragma unroll
                for (int j = 0; j < 8; j++) {
                    const int col = wn * 64 + j * 8 + fc;
                    const float2 o = *reinterpret_cast<const float2*>(
                        &stash[row * STASH_STRIDE + col]);
                    const float cr0 = acc[im][j][hf * 2] + o.x;
                    const float cr1 = acc[im][j][hf * 2 + 1] + o.y;
                    const float d0 = sqrtf(fmaxf(xq + csq_s[col] - 2.f * cr0, EPS_F));
                    const float d1 = sqrtf(fmaxf(xq + csq_s[col + 1] - 2.f * cr1, EPS_F));
                    *reinterpret_cast<float2*>(orow + col) = make_float2(d0, d1);
                }
            }
    }
}

extern "C" void kernel_launch(void* const* d_in, const int* in_sizes, int n_in,
                              void* d_out, int out_size)
{
    const float* X = (const float*)d_in[0];
    const float* C = (const float*)d_in[1];
    float* out = (float*)d_out;

    prep_c_kernel<<<KK, 128>>>(C);

    cudaFuncSetAttribute(rbf_pair_kernel,
                         cudaFuncAttributeMaxDynamicSharedMemorySize, SMEM_BYTES);
    dim3 grid(KK / BN, BB / BM);
    rbf_pair_kernel<<<grid, NTHREADS, SMEM_BYTES>>>(X, out);
}